// round 16
// baseline (speedup 1.0000x reference)
#include <cuda_runtime.h>
#include <cuda_bf16.h>
#include <cstdint>
#include <math.h>

#define B_ 2
#define C_ 1024
#define T_ 2048
#define H_ 16
#define G_ 32
#define QT 128
#define KT 64
#define PAD 72   // bf16 row stride for 64-wide tiles (144B: ldmatrix conflict-free)

// ---------------- scratch (no allocs allowed) ----------------
__device__ __nv_bfloat16  g_xnb [(size_t)B_ * C_ * T_];       // bf16 [b][c][t] (qkv GEMM B)
__device__ __nv_bfloat16  g_qkvb[(size_t)B_ * 3 * C_ * T_];   // qkv [b][3C][t]; v rows stored as f16!
__device__ __nv_bfloat16  g_qT  [(size_t)B_ * H_ * T_ * 64];  // Q^T [bh][t][c] bf16
__device__ __nv_bfloat16  g_kT  [(size_t)B_ * H_ * T_ * 64];  // K^T [bh][t][c] bf16
__device__ __nv_bfloat16  g_biasb[(size_t)T_ * T_];           // qk_bias * log2e, bf16
__device__ float          g_attn[(size_t)B_ * C_ * T_];       // tf32-rounded
__device__ __nv_bfloat16  g_wqb[(size_t)3 * C_ * C_];         // bf16 qkv_w
__device__ float          g_wp [(size_t)C_ * C_];             // tf32-rounded proj_w
__device__ float2         g_stats[B_ * G_];
__device__ float2         g_part[B_ * G_ * 4];

// ---------------- helpers ----------------
__device__ __forceinline__ uint32_t f2tf(float f) {
    uint32_t u;
    asm("cvt.rna.tf32.f32 %0, %1;" : "=r"(u) : "f"(f));
    return u;
}
__device__ __forceinline__ float rtf(float f) { return __uint_as_float(f2tf(f)); }

__device__ __forceinline__ void mma8(float c[4], const uint32_t a[4], const uint32_t b[2]) {
    asm volatile(
        "mma.sync.aligned.m16n8k8.row.col.f32.tf32.tf32.f32 "
        "{%0,%1,%2,%3},{%4,%5,%6,%7},{%8,%9},{%0,%1,%2,%3};\n"
        : "+f"(c[0]), "+f"(c[1]), "+f"(c[2]), "+f"(c[3])
        : "r"(a[0]), "r"(a[1]), "r"(a[2]), "r"(a[3]), "r"(b[0]), "r"(b[1]));
}
__device__ __forceinline__ void mma16(float c[4], const uint32_t a[4], const uint32_t b[2]) {
    asm volatile(
        "mma.sync.aligned.m16n8k16.row.col.f32.bf16.bf16.f32 "
        "{%0,%1,%2,%3},{%4,%5,%6,%7},{%8,%9},{%0,%1,%2,%3};\n"
        : "+f"(c[0]), "+f"(c[1]), "+f"(c[2]), "+f"(c[3])
        : "r"(a[0]), "r"(a[1]), "r"(a[2]), "r"(a[3]), "r"(b[0]), "r"(b[1]));
}
__device__ __forceinline__ void mma16f(float c[4], const uint32_t a[4], const uint32_t b[2]) {
    asm volatile(
        "mma.sync.aligned.m16n8k16.row.col.f32.f16.f16.f32 "
        "{%0,%1,%2,%3},{%4,%5,%6,%7},{%8,%9},{%0,%1,%2,%3};\n"
        : "+f"(c[0]), "+f"(c[1]), "+f"(c[2]), "+f"(c[3])
        : "r"(a[0]), "r"(a[1]), "r"(a[2]), "r"(a[3]), "r"(b[0]), "r"(b[1]));
}
__device__ __forceinline__ void ldsm4(uint32_t& r0, uint32_t& r1, uint32_t& r2, uint32_t& r3,
                                      uint32_t addr) {
    asm volatile("ldmatrix.sync.aligned.m8n8.x4.shared.b16 {%0,%1,%2,%3}, [%4];\n"
                 : "=r"(r0), "=r"(r1), "=r"(r2), "=r"(r3) : "r"(addr));
}
__device__ __forceinline__ void ldsm4t(uint32_t& r0, uint32_t& r1, uint32_t& r2, uint32_t& r3,
                                       uint32_t addr) {
    asm volatile("ldmatrix.sync.aligned.m8n8.x4.trans.shared.b16 {%0,%1,%2,%3}, [%4];\n"
                 : "=r"(r0), "=r"(r1), "=r"(r2), "=r"(r3) : "r"(addr));
}
__device__ __forceinline__ uint32_t bfpack(float lo, float hi) {
    uint32_t d;
    asm("cvt.rn.bf16x2.f32 %0, %1, %2;" : "=r"(d) : "f"(hi), "f"(lo));
    return d;
}
__device__ __forceinline__ uint32_t f16pack(float lo, float hi) {
    uint32_t d;
    asm("cvt.rn.f16x2.f32 %0, %1, %2;" : "=r"(d) : "f"(hi), "f"(lo));
    return d;
}
__device__ __forceinline__ uint32_t ex2h(uint32_t a) {
    uint32_t r;
    asm("ex2.approx.f16x2 %0, %1;" : "=r"(r) : "r"(a));
    return r;
}
__device__ __forceinline__ uint32_t smem_u32(const void* p) {
    return (uint32_t)__cvta_generic_to_shared(p);
}
__device__ __forceinline__ void cpa16(uint32_t dst, const void* src) {
    asm volatile("cp.async.cg.shared.global [%0], [%1], 16;\n" :: "r"(dst), "l"(src));
}
#define CP_COMMIT() asm volatile("cp.async.commit_group;\n")
#define CP_WAIT1()  asm volatile("cp.async.wait_group 1;\n" ::: "memory")
#define CP_WAIT0()  asm volatile("cp.async.wait_group 0;\n" ::: "memory")

// ---------------- 0) merged preprocessing ----------------
__global__ void prep_k(const float* __restrict__ qkv_w, const float* __restrict__ proj_w,
                       const float* __restrict__ qk_bias) {
    const int NQ = 3 * C_ * C_ / 4;
    const int NP = C_ * C_ / 4;
    const int NB = T_ * T_ / 4;
    int i = blockIdx.x * blockDim.x + threadIdx.x;
    if (i < NQ) {
        float4 v = ((const float4*)qkv_w)[i];
        uint2 o;
        o.x = bfpack(v.x, v.y);
        o.y = bfpack(v.z, v.w);
        ((uint2*)g_wqb)[i] = o;
    } else if (i < NQ + NP) {
        int j = i - NQ;
        float4 v = ((const float4*)proj_w)[j];
        v.x = rtf(v.x); v.y = rtf(v.y); v.z = rtf(v.z); v.w = rtf(v.w);
        ((float4*)g_wp)[j] = v;
    } else if (i < NQ + NP + NB) {
        int j = i - NQ - NP;
        const float L = 1.44269504f;
        float4 v = ((const float4*)qk_bias)[j];
        uint2 o;
        o.x = bfpack(v.x * L, v.y * L);
        o.y = bfpack(v.z * L, v.w * L);
        ((uint2*)g_biasb)[j] = o;
    }
}

// ---------------- 1) GroupNorm stats, two-phase ----------------
__global__ void gn_stats1_k(const float* __restrict__ x) {
    __shared__ float ss[256], ss2[256];
    int bg = blockIdx.x >> 2, sl = blockIdx.x & 3;
    const float4* base =
        (const float4*)(x + ((size_t)(bg >> 5) * C_ + (size_t)(bg & 31) * 32) * T_) + sl * 4096;
    float s = 0.f, s2 = 0.f;
    for (int i = threadIdx.x; i < 4096; i += 256) {
        float4 v = base[i];
        s  += (v.x + v.y) + (v.z + v.w);
        s2 += (v.x * v.x + v.y * v.y) + (v.z * v.z + v.w * v.w);
    }
    ss[threadIdx.x] = s; ss2[threadIdx.x] = s2;
    __syncthreads();
    for (int st = 128; st > 0; st >>= 1) {
        if (threadIdx.x < st) {
            ss[threadIdx.x]  += ss[threadIdx.x + st];
            ss2[threadIdx.x] += ss2[threadIdx.x + st];
        }
        __syncthreads();
    }
    if (threadIdx.x == 0) g_part[blockIdx.x] = make_float2(ss[0], ss2[0]);
}
__global__ void gn_stats2_k() {
    int t = threadIdx.x;
    if (t < B_ * G_) {
        float s = 0.f, s2 = 0.f;
#pragma unroll
        for (int j = 0; j < 4; j++) {
            float2 p = g_part[t * 4 + j];
            s += p.x; s2 += p.y;
        }
        const float inv_n = 1.f / (32.f * T_);
        float mean = s * inv_n;
        float var  = s2 * inv_n - mean * mean;
        g_stats[t] = make_float2(mean, rsqrtf(var + 1e-5f));
    }
}

// ---------------- 2) GroupNorm apply (bf16 output only; residual recomputed in proj) ----------------
__global__ void gn_apply_k(const float* __restrict__ x,
                           const float* __restrict__ sc,
                           const float* __restrict__ bi) {
    size_t i4 = (size_t)blockIdx.x * blockDim.x + threadIdx.x;
    size_t i  = i4 * 4;
    if (i >= (size_t)B_ * C_ * T_) return;
    int c = (int)((i / T_) % C_);
    int b = (int)(i / ((size_t)C_ * T_));
    float2 st = g_stats[b * G_ + (c >> 5)];
    float a = st.y * sc[c];
    float d = bi[c] - st.x * a;
    float4 v = *(const float4*)(x + i);
    float4 o;
    o.x = v.x * a + d; o.y = v.y * a + d; o.z = v.z * a + d; o.w = v.w * a + d;
    uint2 p;
    p.x = bfpack(o.x, o.y);
    p.y = bfpack(o.z, o.w);
    *(uint2*)(g_xnb + i) = p;
}

// ---------------- 3) bf16 GEMM (qkv), 3-stage pipeline + fused transpose epilogue ----------------
// v-segment rows are written as f16 (consumed by f16 PV mma in flash).
__global__ void __launch_bounds__(256, 2)
gemm_qkv_k(const __nv_bfloat16* __restrict__ A, const __nv_bfloat16* __restrict__ Bmat,
           const float* __restrict__ bias, __nv_bfloat16* __restrict__ Cout,
           int M, int N, int K) {
    extern __shared__ __nv_bfloat16 bsm[];
    __nv_bfloat16* Ab = bsm;                       // 3 x 128 x 72
    __nv_bfloat16* Bb = bsm + 3 * 128 * 72;        // 3 x 64 x 136
    uint32_t abA = smem_u32(Ab), bbA = smem_u32(Bb);

    int z = blockIdx.z;
    const __nv_bfloat16* Bp = Bmat + (size_t)z * K * N;
    __nv_bfloat16*       Cp = Cout + (size_t)z * M * N;

    int m0 = blockIdx.y * 128, n0 = blockIdx.x * 128;
    int tid = threadIdx.x, lane = tid & 31, w = tid >> 5;
    int wm = w >> 2, wn = w & 3;               // 2 x 4 warps, each 64 x 32
    int g = lane >> 2, t4 = lane & 3;
    int lr = lane & 7, lm = lane >> 3;
    uint32_t aOff = (uint32_t)((((lm & 1) * 8 + lr) * 72 + (lm >> 1) * 8) * 2);
    uint32_t bOff = (uint32_t)((((lm & 1) * 8 + lr) * 136 + (lm >> 1) * 8) * 2);

#define GLOADB(buf, kc)                                                              \
    {                                                                                \
        _Pragma("unroll")                                                            \
        for (int i_ = 0; i_ < 4; i_++) {                                             \
            int j_ = tid + 256 * i_;                                                 \
            int r_ = j_ >> 3, ch_ = j_ & 7;                                          \
            cpa16(abA + (uint32_t)(((buf) * 128 * 72 + r_ * 72 + ch_ * 8) * 2),      \
                  A + (size_t)(m0 + r_) * K + (kc) + ch_ * 8);                       \
        }                                                                            \
        _Pragma("unroll")                                                            \
        for (int i_ = 0; i_ < 4; i_++) {                                             \
            int j_ = tid + 256 * i_;                                                 \
            int r_ = j_ >> 4, ch_ = j_ & 15;                                         \
            cpa16(bbA + (uint32_t)(((buf) * 64 * 136 + r_ * 136 + ch_ * 8) * 2),     \
                  Bp + (size_t)((kc) + r_) * N + n0 + ch_ * 8);                      \
        }                                                                            \
    }

    GLOADB(0, 0); CP_COMMIT();
    GLOADB(1, 64); CP_COMMIT();

    float acc[4][4][4];
#pragma unroll
    for (int i = 0; i < 4; i++)
#pragma unroll
        for (int j = 0; j < 4; j++)
#pragma unroll
            for (int k = 0; k < 4; k++) acc[i][j][k] = 0.f;

    const int nk = K / 64;
    for (int ki = 0; ki < nk; ki++) {
        int cur = ki % 3;
        CP_WAIT1();
        __syncthreads();
        if (ki + 2 < nk) GLOADB((ki + 2) % 3, (ki + 2) * 64);
        CP_COMMIT();

        uint32_t abase = abA + (uint32_t)(cur * 128 * 72 * 2) + aOff;
        uint32_t bbase = bbA + (uint32_t)(cur * 64 * 136 * 2) + bOff;
#pragma unroll
        for (int ks = 0; ks < 4; ks++) {
            uint32_t af[4][4];
#pragma unroll
            for (int mt = 0; mt < 4; mt++)
                ldsm4(af[mt][0], af[mt][1], af[mt][2], af[mt][3],
                      abase + (uint32_t)(((wm * 64 + mt * 16) * 72 + ks * 16) * 2));
            uint32_t bfr[2][4];
#pragma unroll
            for (int np = 0; np < 2; np++)
                ldsm4t(bfr[np][0], bfr[np][1], bfr[np][2], bfr[np][3],
                       bbase + (uint32_t)((ks * 16 * 136 + wn * 32 + np * 16) * 2));
#pragma unroll
            for (int nt = 0; nt < 4; nt++)
#pragma unroll
                for (int mt = 0; mt < 4; mt++)
                    mma16(acc[mt][nt], af[mt], &bfr[nt >> 1][(nt & 1) * 2]);
        }
    }

    // ---- fused epilogue: stage tile (v rows as f16, q/k rows as bf16) ----
    CP_WAIT0();
    __syncthreads();
    __nv_bfloat16* stage = bsm;                    // [128][132] 16-bit
    bool isv = (((m0 >> 6) + wm) % 3) == 2;        // this warp's rows belong to a v segment
#pragma unroll
    for (int mt = 0; mt < 4; mt++) {
        int r0 = wm * 64 + mt * 16 + g;
        float b0 = bias[m0 + r0], b1 = bias[m0 + r0 + 8];
#pragma unroll
        for (int nt = 0; nt < 4; nt++) {
            int cc = wn * 32 + nt * 8 + 2 * t4;
            float v00 = acc[mt][nt][0] + b0, v01 = acc[mt][nt][1] + b0;
            float v10 = acc[mt][nt][2] + b1, v11 = acc[mt][nt][3] + b1;
            *(uint32_t*)&stage[(r0)     * 132 + cc] = isv ? f16pack(v00, v01) : bfpack(v00, v01);
            *(uint32_t*)&stage[(r0 + 8) * 132 + cc] = isv ? f16pack(v10, v11) : bfpack(v10, v11);
        }
    }
    __syncthreads();

#pragma unroll
    for (int sm2 = 0; sm2 < 2; sm2++) {
        int seg64 = (m0 >> 6) + sm2;
        int head = seg64 / 3, which = seg64 % 3;   // 0=q, 1=k, 2=v
        if (which == 2) {
            for (int j = tid; j < 64 * 64; j += 256) {
                int r = j >> 6, cu = j & 63;
                uint32_t v = *(uint32_t*)&stage[(sm2 * 64 + r) * 132 + cu * 2];
                *(uint32_t*)&Cp[(size_t)(m0 + sm2 * 64 + r) * N + n0 + cu * 2] = v;
            }
        } else {
            __nv_bfloat16* dst =
                (which ? g_kT : g_qT) + ((size_t)(z * H_ + head) * T_ + n0) * 64;
            for (int j = tid; j < 128 * 32; j += 256) {
                int t = j >> 5, cu = j & 31;
                unsigned short lo = *(unsigned short*)&stage[(sm2 * 64 + 2 * cu)     * 132 + t];
                unsigned short hi = *(unsigned short*)&stage[(sm2 * 64 + 2 * cu + 1) * 132 + t];
                *(uint32_t*)&dst[(size_t)t * 64 + 2 * cu] = (uint32_t)lo | ((uint32_t)hi << 16);
            }
        }
    }
}

// ---------------- 5) TF32 GEMM (proj), 3-stage pipeline; residual recomputed from x ----------------
__global__ void __launch_bounds__(256, 2)
gemm_k(const float* __restrict__ A, const float* __restrict__ Bmat,
       const float* __restrict__ bias, const float* __restrict__ xraw,
       const float* __restrict__ sc, const float* __restrict__ bi,
       float* __restrict__ Cout, int M, int N, int K) {
    extern __shared__ uint32_t gsm[];
    uint32_t* As = gsm;                       // 3 x 128 x 36
    uint32_t* Bs = gsm + 3 * 128 * 36;        // 3 x 32 x 136
    uint32_t asA = smem_u32(As), bsA = smem_u32(Bs);

    int z = blockIdx.z;
    const float* Bp = Bmat + (size_t)z * K * N;
    const float* Xp = xraw + (size_t)z * M * N;
    float*       Cp = Cout + (size_t)z * M * N;

    int m0 = blockIdx.y * 128, n0 = blockIdx.x * 128;
    int tid = threadIdx.x, lane = tid & 31, w = tid >> 5;
    int wm = w >> 2, wn = w & 3;
    int g = lane >> 2, t4 = lane & 3;
    int lr = lane & 7, lm = lane >> 3;
    uint32_t aOff = (uint32_t)((((lm & 1) * 8 + lr) * 36 + (lm >> 1) * 4) * 4);

#define GLOAD(buf, kc)                                                              \
    {                                                                               \
        _Pragma("unroll")                                                           \
        for (int i_ = 0; i_ < 4; i_++) {                                            \
            int j_ = tid + 256 * i_;                                                \
            int r_ = j_ >> 3, ch_ = j_ & 7;                                         \
            cpa16(asA + (uint32_t)(((buf) * 128 * 36 + r_ * 36 + ch_ * 4) * 4),     \
                  A + (size_t)(m0 + r_) * K + (kc) + ch_ * 4);                      \
        }                                                                           \
        _Pragma("unroll")                                                           \
        for (int i_ = 0; i_ < 4; i_++) {                                            \
            int j_ = tid + 256 * i_;                                                \
            int r_ = j_ >> 5, ch_ = j_ & 31;                                        \
            cpa16(bsA + (uint32_t)(((buf) * 32 * 136 + r_ * 136 + ch_ * 4) * 4),    \
                  Bp + (size_t)((kc) + r_) * N + n0 + ch_ * 4);                     \
        }                                                                           \
    }

    GLOAD(0, 0); CP_COMMIT();
    GLOAD(1, 32); CP_COMMIT();

    float acc[4][4][4];
#pragma unroll
    for (int i = 0; i < 4; i++)
#pragma unroll
        for (int j = 0; j < 4; j++)
#pragma unroll
            for (int k = 0; k < 4; k++) acc[i][j][k] = 0.f;

    const int nk = K / 32;
    for (int ki = 0; ki < nk; ki++) {
        int cur = ki % 3;
        CP_WAIT1();
        __syncthreads();
        if (ki + 2 < nk) GLOAD((ki + 2) % 3, (ki + 2) * 32);
        CP_COMMIT();

        const uint32_t* Bb = Bs + cur * 32 * 136;
        uint32_t abase = asA + (uint32_t)(cur * 128 * 36 * 4) + aOff;
#pragma unroll
        for (int ks8 = 0; ks8 < 4; ks8++) {
            uint32_t af[4][4];
#pragma unroll
            for (int mt = 0; mt < 4; mt++)
                ldsm4(af[mt][0], af[mt][1], af[mt][2], af[mt][3],
                      abase + (uint32_t)(((wm * 64 + mt * 16) * 36 + ks8 * 8) * 4));
#pragma unroll
            for (int nt = 0; nt < 4; nt++) {
                uint32_t bf[2];
                int nc = wn * 32 + nt * 8;
                bf[0] = Bb[(ks8 * 8 + t4) * 136 + nc + g];
                bf[1] = Bb[(ks8 * 8 + 4 + t4) * 136 + nc + g];
#pragma unroll
                for (int mt = 0; mt < 4; mt++) mma8(acc[mt][nt], af[mt], bf);
            }
        }
    }

#pragma unroll
    for (int mt = 0; mt < 4; mt++) {
        int r0 = m0 + wm * 64 + mt * 16 + g;
        float b0 = bias[r0], b1 = bias[r0 + 8];
        float2 st0 = g_stats[z * G_ + (r0 >> 5)];
        float2 st1 = g_stats[z * G_ + ((r0 + 8) >> 5)];
        float ga0 = st0.y * sc[r0],     gd0 = bi[r0]     - st0.x * ga0;
        float ga1 = st1.y * sc[r0 + 8], gd1 = bi[r0 + 8] - st1.x * ga1;
#pragma unroll
        for (int nt = 0; nt < 4; nt++) {
            int cc = n0 + wn * 32 + nt * 8 + 2 * t4;
            size_t o0 = (size_t)r0 * N + cc;
            size_t o1 = (size_t)(r0 + 8) * N + cc;
            float2 v0 = make_float2(acc[mt][nt][0] + b0 + (Xp[o0]     * ga0 + gd0),
                                    acc[mt][nt][1] + b0 + (Xp[o0 + 1] * ga0 + gd0));
            float2 v1 = make_float2(acc[mt][nt][2] + b1 + (Xp[o1]     * ga1 + gd1),
                                    acc[mt][nt][3] + b1 + (Xp[o1 + 1] * ga1 + gd1));
            *(float2*)&Cp[o0] = v0;
            *(float2*)&Cp[o1] = v1;
        }
    }
}

// ---------------- 4) flash attention: no-max exp2-f16 softmax, hoisted bias loads ----------------
// smem bf16: Qs[128][72] | K[3][64][72] | V[3][64][72] = 73,728 B
__global__ void __launch_bounds__(256, 2)
flash_k(float* __restrict__ aout) {
    extern __shared__ __nv_bfloat16 fsm[];
    __nv_bfloat16* Qs = fsm;                          // 128 x 72
    __nv_bfloat16* KtB = fsm + QT * PAD;              // 3 x 64 x 72
    __nv_bfloat16* VsB = KtB + 3 * KT * PAD;          // 3 x 64 x 72

    int qb = (int)(gridDim.x - 1) - blockIdx.x;       // heavy blocks first
    int bh = blockIdx.y;
    int b = bh >> 4, h = bh & 15;
    const __nv_bfloat16* qTp = g_qT + (size_t)bh * T_ * 64;
    const __nv_bfloat16* kTp = g_kT + (size_t)bh * T_ * 64;
    const __nv_bfloat16* vp  = g_qkvb + ((size_t)b * 3 * C_ + (size_t)h * 192 + 128) * T_;

    int tid = threadIdx.x, lane = tid & 31, w = tid >> 5;
    int g = lane >> 2, t4 = lane & 3;
    int tb = w * 16;
    int tq0 = qb * QT + tb + g, tq1 = tq0 + 8;
    const __nv_bfloat16* bp0 = g_biasb + (size_t)tq0 * T_;
    const __nv_bfloat16* bp1 = g_biasb + (size_t)tq1 * T_;

    uint32_t qsA = smem_u32(Qs);
    uint32_t ktA[3] = { smem_u32(KtB), smem_u32(KtB + KT * PAD), smem_u32(KtB + 2 * KT * PAD) };
    uint32_t vsA[3] = { smem_u32(VsB), smem_u32(VsB + KT * PAD), smem_u32(VsB + 2 * KT * PAD) };

    int lr = lane & 7, part = lane >> 3;
    uint32_t bOff = (uint32_t)(((((part >> 1) * 8) + lr) * PAD + (part & 1) * 8) * 2);
    uint32_t aOff = (uint32_t)(((((part & 1) * 8) + lr) * PAD + (part >> 1) * 8) * 2);

    const int kbmax = 2 * qb + 1;
    const float SC = 0.18033688f;                     // 0.125 * log2(e)
    const uint32_t ONES2 = 0x3C003C00u;               // f16 {1,1}

    // ---- prologue ----
    for (int j = tid; j < 1024; j += 256) {
        int r = j >> 3, ch = j & 7;
        cpa16(qsA + (uint32_t)((r * PAD + ch * 8) * 2),
              qTp + (size_t)(qb * QT + r) * 64 + ch * 8);
    }
    for (int j = tid; j < 512; j += 256) {
        int r = j >> 3, ch = j & 7;
        cpa16(ktA[0] + (uint32_t)((r * PAD + ch * 8) * 2), kTp + (size_t)r * 64 + ch * 8);
        cpa16(vsA[0] + (uint32_t)((r * PAD + ch * 8) * 2), vp + (size_t)r * T_ + ch * 8);
    }
    CP_COMMIT();
    for (int j = tid; j < 512; j += 256) {
        int r = j >> 3, ch = j & 7;
        cpa16(ktA[1] + (uint32_t)((r * PAD + ch * 8) * 2),
              kTp + (size_t)(KT + r) * 64 + ch * 8);
        cpa16(vsA[1] + (uint32_t)((r * PAD + ch * 8) * 2),
              vp + (size_t)r * T_ + KT + ch * 8);
    }
    CP_COMMIT();

    float o[9][4];                                    // o[8] = ones-column row sums (l)
#pragma unroll
    for (int i = 0; i < 9; i++)
#pragma unroll
        for (int j = 0; j < 4; j++) o[i][j] = 0.f;

    uint32_t Qf[4][4];
    bool qloaded = false;

    for (int kb = 0; kb <= kbmax; kb++) {
        int cur = kb % 3;
        CP_WAIT1();
        __syncthreads();

        if (!qloaded) {
            qloaded = true;
#pragma unroll
            for (int ks = 0; ks < 4; ks++)
                ldsm4(Qf[ks][0], Qf[ks][1], Qf[ks][2], Qf[ks][3],
                      qsA + aOff + (uint32_t)((tb * PAD + ks * 16) * 2));
        }

        if (kb + 2 <= kbmax) {
            int nb = (kb + 2) % 3;
            const __nv_bfloat16* ksrc = kTp + (size_t)(kb + 2) * KT * 64;
            const __nv_bfloat16* vsrc = vp + (size_t)(kb + 2) * KT;
            for (int j = tid; j < 512; j += 256) {
                int r = j >> 3, ch = j & 7;
                cpa16(ktA[nb] + (uint32_t)((r * PAD + ch * 8) * 2),
                      ksrc + (size_t)r * 64 + ch * 8);
                cpa16(vsA[nb] + (uint32_t)((r * PAD + ch * 8) * 2),
                      vsrc + (size_t)r * T_ + ch * 8);
            }
        }
        CP_COMMIT();

        // ---- hoisted bias loads (consumed after the S-mma stream) ----
        uint32_t ub0[8], ub1[8];
#pragma unroll
        for (int nt = 0; nt < 8; nt++) {
            int sg = kb * KT + nt * 8 + 2 * t4;
            ub0[nt] = *(const uint32_t*)(bp0 + sg);
            ub1[nt] = *(const uint32_t*)(bp1 + sg);
        }

        uint32_t kcur = ktA[cur] + bOff;
        uint32_t vcur = vsA[cur] + bOff;

        // ---- S = Q K^T ----
        float s[8][4];
#pragma unroll
        for (int i = 0; i < 8; i++)
#pragma unroll
            for (int j = 0; j < 4; j++) s[i][j] = 0.f;

#pragma unroll
        for (int ks = 0; ks < 4; ks++) {
            uint32_t bfr[16];
#pragma unroll
            for (int np = 0; np < 4; np++)
                ldsm4(bfr[np * 4], bfr[np * 4 + 1], bfr[np * 4 + 2], bfr[np * 4 + 3],
                      kcur + (uint32_t)(((np * 16) * PAD + ks * 16) * 2));
#pragma unroll
            for (int nt = 0; nt < 8; nt++)
                mma16(s[nt], Qf[ks], &bfr[(nt >> 1) * 4 + (nt & 1) * 2]);
        }

        // ---- scale + bias (log2 domain) + causal mask ----
        bool diag = (kb * KT + KT - 1 > qb * QT + tb);
#pragma unroll
        for (int nt = 0; nt < 8; nt++) {
            int sg = kb * KT + nt * 8 + 2 * t4;
            s[nt][0] = s[nt][0] * SC + __uint_as_float(ub0[nt] << 16);
            s[nt][1] = s[nt][1] * SC + __uint_as_float(ub0[nt] & 0xFFFF0000u);
            s[nt][2] = s[nt][2] * SC + __uint_as_float(ub1[nt] << 16);
            s[nt][3] = s[nt][3] * SC + __uint_as_float(ub1[nt] & 0xFFFF0000u);
            if (diag) {
                if (sg     > tq0) s[nt][0] = -1e30f;
                if (sg + 1 > tq0) s[nt][1] = -1e30f;
                if (sg     > tq1) s[nt][2] = -1e30f;
                if (sg + 1 > tq1) s[nt][3] = -1e30f;
            }
        }

        // ---- P = exp2(s), f16x2 (no max subtraction; logits bounded) ----
        uint32_t hlo[8], hhi[8];
#pragma unroll
        for (int nt = 0; nt < 8; nt++) {
            hlo[nt] = ex2h(f16pack(s[nt][0], s[nt][1]));
            hhi[nt] = ex2h(f16pack(s[nt][2], s[nt][3]));
        }

        // ---- O += P V^T (f16), ones column accumulates row sums ----
#pragma unroll
        for (int ks = 0; ks < 4; ks++) {
            uint32_t pa[4] = { hlo[2 * ks], hhi[2 * ks], hlo[2 * ks + 1], hhi[2 * ks + 1] };

            uint32_t bfr[16];
#pragma unroll
            for (int np = 0; np < 4; np++)
                ldsm4(bfr[np * 4], bfr[np * 4 + 1], bfr[np * 4 + 2], bfr[np * 4 + 3],
                      vcur + (uint32_t)(((np * 16) * PAD + ks * 16) * 2));
#pragma unroll
            for (int nt = 0; nt < 8; nt++)
                mma16f(o[nt], pa, &bfr[(nt >> 1) * 4 + (nt & 1) * 2]);
            uint32_t onesb[2] = { ONES2, ONES2 };
            mma16f(o[8], pa, onesb);
        }
    }

    // ---- epilogue: every lane holds its rows' sums in o[8][0] / o[8][2] ----
    float i0 = 1.f / o[8][0], i1 = 1.f / o[8][2];
    float* Os = (float*)fsm;                 // 64 x 132 f32 fits in 73,728 B
    __syncthreads();
#pragma unroll
    for (int nt = 0; nt < 8; nt++) {
        int col = nt * 8 + 2 * t4;
        Os[(col)     * 132 + tb + g]     = rtf(o[nt][0] * i0);
        Os[(col + 1) * 132 + tb + g]     = rtf(o[nt][1] * i0);
        Os[(col)     * 132 + tb + 8 + g] = rtf(o[nt][2] * i1);
        Os[(col + 1) * 132 + tb + 8 + g] = rtf(o[nt][3] * i1);
    }
    __syncthreads();
    for (int j = tid; j < 64 * QT; j += 256) {
        int c = j >> 7, tl = j & 127;
        aout[((size_t)b * C_ + h * 64 + c) * T_ + qb * QT + tl] = Os[c * 132 + tl];
    }
}

// ---------------- launch ----------------
extern "C" void kernel_launch(void* const* d_in, const int* in_sizes, int n_in,
                              void* d_out, int out_size) {
    const float* x        = (const float*)d_in[0];
    // d_in[1] = mask (tril; encoded by causal loop structure)
    const float* qk_bias  = (const float*)d_in[2];
    const float* gn_scale = (const float*)d_in[3];
    const float* gn_bias  = (const float*)d_in[4];
    const float* qkv_w    = (const float*)d_in[5];
    const float* qkv_b    = (const float*)d_in[6];
    const float* proj_w   = (const float*)d_in[7];
    const float* proj_b   = (const float*)d_in[8];
    float* out = (float*)d_out;

    float *attn, *wp;
    __nv_bfloat16 *xnb, *qkvb, *wqb;
    cudaGetSymbolAddress((void**)&xnb,  g_xnb);
    cudaGetSymbolAddress((void**)&qkvb, g_qkvb);
    cudaGetSymbolAddress((void**)&attn, g_attn);
    cudaGetSymbolAddress((void**)&wqb,  g_wqb);
    cudaGetSymbolAddress((void**)&wp,   g_wp);

    const int NPREP = 3 * C_ * C_ / 4 + C_ * C_ / 4 + T_ * T_ / 4;
    prep_k<<<(NPREP + 255) / 256, 256>>>(qkv_w, proj_w, qk_bias);

    gn_stats1_k<<<B_ * G_ * 4, 256>>>(x);
    gn_stats2_k<<<1, 64>>>();
    int n4 = (B_ * C_ * T_) / 4;
    gn_apply_k<<<(n4 + 255) / 256, 256>>>(x, gn_scale, gn_bias);

    const int BSMEM = 3 * (128 * 72 + 64 * 136) * 2;       // 107,520 B
    cudaFuncSetAttribute(gemm_qkv_k, cudaFuncAttributeMaxDynamicSharedMemorySize, BSMEM);
    gemm_qkv_k<<<dim3(T_ / 128, (3 * C_) / 128, B_), 256, BSMEM>>>(
        wqb, xnb, qkv_b, qkvb, 3 * C_, T_, C_);

    const int FSMEM = (QT * PAD + 6 * KT * PAD) * 2;       // 73,728 B
    cudaFuncSetAttribute(flash_k, cudaFuncAttributeMaxDynamicSharedMemorySize, FSMEM);
    flash_k<<<dim3(T_ / QT, B_ * H_), 256, FSMEM>>>(attn);

    const int GSMEM = 3 * (128 * 36 + 32 * 136) * 4;       // 107,520 B
    cudaFuncSetAttribute(gemm_k, cudaFuncAttributeMaxDynamicSharedMemorySize, GSMEM);
    gemm_k<<<dim3(T_ / 128, C_ / 128, B_), 256, GSMEM>>>(
        wp, attn, proj_b, x, gn_scale, gn_bias, out, C_, T_, C_);
}